// round 1
// baseline (speedup 1.0000x reference)
#include <cuda_runtime.h>
#include <math.h>

#define NBATCH 32
#define TT 1024
#define CC 512
#define KK 64
#define FEPS 1e-12f

// Scratch (allocation-free rule: __device__ globals)
__device__ float g_a[(size_t)NBATCH * TT * KK];      // [n][t][k] softmax weights, 8MB
__device__ float g_asumP[NBATCH * 8 * KK];           // per-(n, t-block) partial sums of a over t
__device__ float g_rown2[NBATCH * KK];               // post-intra-norm row energy

// ---------------------------------------------------------------------------
// Kernel A: logits = x @ W^T + b  (per (n,t) row), softmax over K -> g_a
// Tile: 128 t x 64 k, reduction over C in chunks of 32. 256 threads,
// micro-tile 8t x 4k per thread.
// ---------------------------------------------------------------------------
struct SmemA {
    union {
        struct {
            float X[128][32];   // x tile, t-major
            float Wt[32][68];   // W tile transposed (c-major), padded row
        } p1;
        float L[128][68];       // logits / softmax buffer (reuses space)
    };
};

__global__ __launch_bounds__(256) void kA(const float* __restrict__ x,
                                          const float* __restrict__ W,
                                          const float* __restrict__ b) {
    const int n  = blockIdx.y;
    const int t0 = blockIdx.x * 128;
    const int tid = threadIdx.x;
    const int tx = tid & 15;    // k-group (4 k's)
    const int ty = tid >> 4;    // t-group (8 t's)

    __shared__ __align__(16) SmemA sm;
    __shared__ float sInv[128];

    float acc[8][4];
#pragma unroll
    for (int i = 0; i < 8; i++)
#pragma unroll
        for (int j = 0; j < 4; j++) acc[i][j] = 0.f;

    const float* xn = x + ((size_t)n * TT + t0) * CC;

    for (int cc = 0; cc < CC; cc += 32) {
        // load x tile: 128 x 32 floats (1024 float4), coalesced
#pragma unroll
        for (int it = 0; it < 4; it++) {
            int idx = tid + it * 256;       // float4 index
            int t   = idx >> 3;             // 8 float4 per 32-float row
            int c4  = idx & 7;
            *(float4*)&sm.p1.X[t][c4 * 4] =
                *(const float4*)(xn + (size_t)t * CC + cc + c4 * 4);
        }
        // load W tile transposed: read coalesced in c, store [c][k]
#pragma unroll
        for (int it = 0; it < 8; it++) {
            int idx = tid + it * 256;       // scalar index, 2048 total
            int k   = idx >> 5;
            int c   = idx & 31;
            sm.p1.Wt[c][k] = W[k * CC + cc + c];
        }
        __syncthreads();
#pragma unroll
        for (int c = 0; c < 32; c++) {
            float4 w4 = *(const float4*)&sm.p1.Wt[c][tx * 4];
#pragma unroll
            for (int i = 0; i < 8; i++) {
                float xv = sm.p1.X[ty * 8 + i][c];
                acc[i][0] = fmaf(xv, w4.x, acc[i][0]);
                acc[i][1] = fmaf(xv, w4.y, acc[i][1]);
                acc[i][2] = fmaf(xv, w4.z, acc[i][2]);
                acc[i][3] = fmaf(xv, w4.w, acc[i][3]);
            }
        }
        __syncthreads();
    }

    // + bias, stash logits in smem
    float4 b4 = *(const float4*)&b[tx * 4];
#pragma unroll
    for (int i = 0; i < 8; i++) {
        int t = ty * 8 + i;
        sm.L[t][tx * 4 + 0] = acc[i][0] + b4.x;
        sm.L[t][tx * 4 + 1] = acc[i][1] + b4.y;
        sm.L[t][tx * 4 + 2] = acc[i][2] + b4.z;
        sm.L[t][tx * 4 + 3] = acc[i][3] + b4.w;
    }
    __syncthreads();

    // softmax over K=64 per t-row (threads 0..127 each own one row)
    if (tid < 128) {
        float m = -1e30f;
#pragma unroll
        for (int k = 0; k < KK; k++) m = fmaxf(m, sm.L[tid][k]);
        float s = 0.f;
#pragma unroll
        for (int k = 0; k < KK; k++) {
            float e = __expf(sm.L[tid][k] - m);
            sm.L[tid][k] = e;
            s += e;
        }
        sInv[tid] = 1.f / s;
    }
    __syncthreads();

    // scale + write a to global; also write scaled values back to smem for asum
    float* ga = g_a + ((size_t)n * TT + t0) * KK;
#pragma unroll
    for (int it = 0; it < 8; it++) {
        int idx = tid + it * 256;   // float4 index, 2048 total (128 rows x 16)
        int t   = idx >> 4;
        int q   = idx & 15;
        float inv = sInv[t];
        float4 v = *(float4*)&sm.L[t][q * 4];
        v.x *= inv; v.y *= inv; v.z *= inv; v.w *= inv;
        *(float4*)&ga[(size_t)t * KK + q * 4] = v;
        *(float4*)&sm.L[t][q * 4] = v;
    }
    __syncthreads();

    // per-k partial sum over this block's 128 t's (deterministic, no atomics)
    if (tid < KK) {
        float s = 0.f;
        for (int t = 0; t < 128; t++) s += sm.L[t][tid];
        g_asumP[(n * 8 + blockIdx.x) * KK + tid] = s;
    }
}

// ---------------------------------------------------------------------------
// Kernel B: vlad[n,k,c] = sum_t a[n,t,k]*x[n,t,c]  -  asum[n,k]*cent[k,c]
// Tile: 64 k x 64 c, reduction over T in chunks of 32. 256 threads,
// micro-tile 4k x 4c.
// ---------------------------------------------------------------------------
__global__ __launch_bounds__(256) void kB(const float* __restrict__ x,
                                          const float* __restrict__ cent,
                                          float* __restrict__ out) {
    const int n  = blockIdx.y;
    const int cc = blockIdx.x * 64;
    const int tid = threadIdx.x;
    const int tx = tid & 15;    // k-group
    const int ty = tid >> 4;    // c-group

    __shared__ __align__(16) float sA[32][68];
    __shared__ __align__(16) float sX[32][68];
    __shared__ float sAsum[KK];

    if (tid < KK) {
        float s = 0.f;
#pragma unroll
        for (int tb = 0; tb < 8; tb++) s += g_asumP[(n * 8 + tb) * KK + tid];
        sAsum[tid] = s;
    }

    float acc[4][4];
#pragma unroll
    for (int j = 0; j < 4; j++)
#pragma unroll
        for (int i = 0; i < 4; i++) acc[j][i] = 0.f;

    const float* ga = g_a + (size_t)n * TT * KK;
    const float* xn = x + (size_t)n * TT * CC;

    for (int tt = 0; tt < TT; tt += 32) {
#pragma unroll
        for (int it = 0; it < 2; it++) {
            int idx = tid + it * 256;   // float4 index, 512 per buffer
            int t   = idx >> 4;
            int q   = idx & 15;
            *(float4*)&sA[t][q * 4] = *(const float4*)&ga[(size_t)(tt + t) * KK + q * 4];
            *(float4*)&sX[t][q * 4] = *(const float4*)&xn[(size_t)(tt + t) * CC + cc + q * 4];
        }
        __syncthreads();
#pragma unroll
        for (int t = 0; t < 32; t++) {
            float4 a4 = *(const float4*)&sA[t][tx * 4];
            float4 x4 = *(const float4*)&sX[t][ty * 4];
            acc[0][0] = fmaf(a4.x, x4.x, acc[0][0]);
            acc[0][1] = fmaf(a4.x, x4.y, acc[0][1]);
            acc[0][2] = fmaf(a4.x, x4.z, acc[0][2]);
            acc[0][3] = fmaf(a4.x, x4.w, acc[0][3]);
            acc[1][0] = fmaf(a4.y, x4.x, acc[1][0]);
            acc[1][1] = fmaf(a4.y, x4.y, acc[1][1]);
            acc[1][2] = fmaf(a4.y, x4.z, acc[1][2]);
            acc[1][3] = fmaf(a4.y, x4.w, acc[1][3]);
            acc[2][0] = fmaf(a4.z, x4.x, acc[2][0]);
            acc[2][1] = fmaf(a4.z, x4.y, acc[2][1]);
            acc[2][2] = fmaf(a4.z, x4.z, acc[2][2]);
            acc[2][3] = fmaf(a4.z, x4.w, acc[2][3]);
            acc[3][0] = fmaf(a4.w, x4.x, acc[3][0]);
            acc[3][1] = fmaf(a4.w, x4.y, acc[3][1]);
            acc[3][2] = fmaf(a4.w, x4.z, acc[3][2]);
            acc[3][3] = fmaf(a4.w, x4.w, acc[3][3]);
        }
        __syncthreads();
    }

    float* on = out + (size_t)n * KK * CC;
#pragma unroll
    for (int j = 0; j < 4; j++) {
        int k = tx * 4 + j;
        float as = sAsum[k];
        float4 c4 = *(const float4*)&cent[k * CC + cc + ty * 4];
        float4 v;
        v.x = acc[j][0] - as * c4.x;
        v.y = acc[j][1] - as * c4.y;
        v.z = acc[j][2] - as * c4.z;
        v.w = acc[j][3] - as * c4.w;
        *(float4*)&on[(size_t)k * CC + cc + ty * 4] = v;
    }
}

// ---------------------------------------------------------------------------
// Kernel C: intra-normalize each (n,k) row of 512, record post-norm energy
// ---------------------------------------------------------------------------
__global__ __launch_bounds__(128) void kC(float* __restrict__ out) {
    const int row = blockIdx.x;            // n*K + k
    const int tid = threadIdx.x;
    float4 v = *(float4*)&out[(size_t)row * CC + tid * 4];
    float ss = v.x * v.x + v.y * v.y + v.z * v.z + v.w * v.w;
#pragma unroll
    for (int o = 16; o > 0; o >>= 1) ss += __shfl_xor_sync(0xffffffffu, ss, o);
    __shared__ float red[4];
    if ((tid & 31) == 0) red[tid >> 5] = ss;
    __syncthreads();
    float tot = red[0] + red[1] + red[2] + red[3];
    float inv = 1.f / fmaxf(sqrtf(tot), FEPS);
    v.x *= inv; v.y *= inv; v.z *= inv; v.w *= inv;
    *(float4*)&out[(size_t)row * CC + tid * 4] = v;
    if (tid == 0) g_rown2[row] = tot * inv * inv;
}

// ---------------------------------------------------------------------------
// Kernel D: global L2 normalize per n
// ---------------------------------------------------------------------------
__global__ __launch_bounds__(256) void kD(float* __restrict__ out) {
    const int n = blockIdx.x;
    __shared__ float sScale;
    if (threadIdx.x == 0) {
        float s = 0.f;
        for (int k = 0; k < KK; k++) s += g_rown2[n * KK + k];
        sScale = 1.f / fmaxf(sqrtf(s), FEPS);
    }
    __syncthreads();
    float sc = sScale;
    float* on = out + (size_t)n * KK * CC;
    for (int i = threadIdx.x; i < KK * CC / 4; i += 256) {
        float4 v = *(float4*)&on[i * 4];
        v.x *= sc; v.y *= sc; v.z *= sc; v.w *= sc;
        *(float4*)&on[i * 4] = v;
    }
}

extern "C" void kernel_launch(void* const* d_in, const int* in_sizes, int n_in,
                              void* d_out, int out_size) {
    const float* x    = (const float*)d_in[0];  // [32,1024,512]
    const float* W    = (const float*)d_in[1];  // [64,512]
    const float* b    = (const float*)d_in[2];  // [64]
    const float* cent = (const float*)d_in[3];  // [64,512]
    float* out = (float*)d_out;                 // [32, 32768]

    kA<<<dim3(8, NBATCH), 256>>>(x, W, b);
    kB<<<dim3(8, NBATCH), 256>>>(x, cent, out);
    kC<<<NBATCH * KK, 128>>>(out);
    kD<<<NBATCH, 256>>>(out);
}

// round 3
// speedup vs baseline: 1.4131x; 1.4131x over previous
#include <cuda_runtime.h>
#include <cuda_bf16.h>
#include <stdint.h>
#include <math.h>

#define NB 32
#define TT 1024
#define CC 512
#define KK 64
#define FEPS 1e-12f

// operand tile row stride: 72 bf16 = 144 bytes (conflict-free fragment LDS)
#define STRB 144

// kA smem layout (bytes)
#define A_XH 0            // 128 x 72 bf16 = 18432
#define A_XL 18432
#define A_WH 36864        // 64 x 72 bf16 = 9216
#define A_WL 46080
// kB smem layout
#define B_XH 0            // xT 128 x 72 bf16
#define B_XL 18432
#define B_AH 36864        // aT 64 x 72 bf16
#define B_AL 46080
// epilogue overlays (post-sync reuse of operand region)
#define O_SL 0            // kA logits: 128 rows x 65 f32 = 33280
#define O_ST 33280        // kA softmax^T: 64 x 132 f32 = 33792 (ends 67072)
#define O_SC 0            // kB centroid tile: 64 x 132 f32
#define O_SO 33792        // kB output tile: 64 x 132 f32 (ends 67584)
#define O_AUX 67584       // 64 floats (bias / asum)
#define SMEM_BYTES 68608

// ---- scratch (__device__ globals: allocation-free rule) ----
__device__ __align__(16) __nv_bfloat16 g_aTh[(size_t)NB * KK * TT]; // a^T hi [n][k][t]
__device__ __align__(16) __nv_bfloat16 g_aTl[(size_t)NB * KK * TT]; // a^T lo
__device__ __align__(16) __nv_bfloat16 g_Wh[KK * CC];
__device__ __align__(16) __nv_bfloat16 g_Wl[KK * CC];
__device__ float g_asumP[NB * 8 * KK];   // per (n, t-tile, k) sum of a
__device__ float g_sqP[NB * 4 * KK];     // per (n, c-tile, k) sum of vlad^2

__device__ __forceinline__ uint32_t b2u(__nv_bfloat162 v) { return *reinterpret_cast<uint32_t*>(&v); }

__device__ __forceinline__ void split_pair(float f0, float f1, __nv_bfloat162& h, __nv_bfloat162& l) {
    h = __floats2bfloat162_rn(f0, f1);
    float2 hf = __bfloat1622float2(h);
    l = __floats2bfloat162_rn(f0 - hf.x, f1 - hf.y);
}

__device__ __forceinline__ void mma16816(float* d, const uint32_t* a, const uint32_t* b) {
    asm volatile("mma.sync.aligned.m16n8k16.row.col.f32.bf16.bf16.f32 "
                 "{%0,%1,%2,%3}, {%4,%5,%6,%7}, {%8,%9}, {%0,%1,%2,%3};"
                 : "+f"(d[0]), "+f"(d[1]), "+f"(d[2]), "+f"(d[3])
                 : "r"(a[0]), "r"(a[1]), "r"(a[2]), "r"(a[3]), "r"(b[0]), "r"(b[1]));
}

// ---------------------------------------------------------------------------
// kW: split W into bf16 hi/lo
// ---------------------------------------------------------------------------
__global__ void kW(const float* __restrict__ W) {
    int i = blockIdx.x * 256 + threadIdx.x;
    if (i < KK * CC) {
        float v = W[i];
        __nv_bfloat16 h = __float2bfloat16(v);
        g_Wh[i] = h;
        g_Wl[i] = __float2bfloat16(v - __bfloat162float(h));
    }
}

// ---------------------------------------------------------------------------
// kA: logits[128t x 64k] = x @ W^T (bf16 3-term split HMMA) + bias + softmax
//     -> a^T bf16 pairs [n][k][t] + asum partials
// grid (8 t-tiles, 32 n), 256 threads (8 warps: 4 t-groups x 2 k-groups)
// ---------------------------------------------------------------------------
__global__ __launch_bounds__(256, 2) void kA(const float* __restrict__ x,
                                             const float* __restrict__ b) {
    extern __shared__ __align__(16) char sm[];
    const int n = blockIdx.y, tile = blockIdx.x, t0 = tile * 128;
    const int tid = threadIdx.x, wid = tid >> 5, lane = tid & 31;
    const int wt = (wid & 3) * 32, wk = (wid >> 2) * 32;
    float* sAux = (float*)(sm + O_AUX);
    if (tid < KK) sAux[tid] = b[tid];

    float d[2][4][4];
#pragma unroll
    for (int mt = 0; mt < 2; mt++)
#pragma unroll
        for (int nt = 0; nt < 4; nt++)
#pragma unroll
            for (int j = 0; j < 4; j++) d[mt][nt][j] = 0.f;

    const float* xn = x + ((size_t)n * TT + t0) * CC;

    for (int ch = 0; ch < 8; ch++) {
        // X tile 128t x 64c: fp32 load, split, store [t][c]
#pragma unroll
        for (int it = 0; it < 8; it++) {
            int idx = tid + it * 256;
            int t = idx >> 4, c4 = idx & 15;
            float4 v = *(const float4*)(xn + (size_t)t * CC + ch * 64 + c4 * 4);
            __nv_bfloat162 h0, l0, h1, l1;
            split_pair(v.x, v.y, h0, l0);
            split_pair(v.z, v.w, h1, l1);
            uint32_t off = (uint32_t)(t * STRB + c4 * 8);
            *(uint2*)(sm + A_XH + off) = make_uint2(b2u(h0), b2u(h1));
            *(uint2*)(sm + A_XL + off) = make_uint2(b2u(l0), b2u(l1));
        }
        // W tile 64k x 64c bf16 copy
#pragma unroll
        for (int it = 0; it < 2; it++) {
            int idx = tid + it * 256;
            int k = idx >> 3, seg = idx & 7;
            uint32_t off = (uint32_t)(k * STRB + seg * 16);
            *(uint4*)(sm + A_WH + off) = *(const uint4*)&g_Wh[k * CC + ch * 64 + seg * 8];
            *(uint4*)(sm + A_WL + off) = *(const uint4*)&g_Wl[k * CC + ch * 64 + seg * 8];
        }
        __syncthreads();

        const int ra = lane >> 2;
        const int cb2 = (lane & 3) * 2;
#pragma unroll
        for (int ks = 0; ks < 4; ks++) {
            int cs = ks * 16 + cb2;
            uint32_t ah[2][4], al[2][4];
#pragma unroll
            for (int mt = 0; mt < 2; mt++) {
                const char* p = sm + (wt + mt * 16 + ra) * STRB + cs * 2;
                ah[mt][0] = *(const uint32_t*)(p + A_XH);
                ah[mt][1] = *(const uint32_t*)(p + A_XH + 8 * STRB);
                ah[mt][2] = *(const uint32_t*)(p + A_XH + 16);
                ah[mt][3] = *(const uint32_t*)(p + A_XH + 8 * STRB + 16);
                al[mt][0] = *(const uint32_t*)(p + A_XL);
                al[mt][1] = *(const uint32_t*)(p + A_XL + 8 * STRB);
                al[mt][2] = *(const uint32_t*)(p + A_XL + 16);
                al[mt][3] = *(const uint32_t*)(p + A_XL + 8 * STRB + 16);
            }
            uint32_t bh[4][2], bl[4][2];
#pragma unroll
            for (int nt = 0; nt < 4; nt++) {
                const char* p = sm + (wk + nt * 8 + ra) * STRB + cs * 2;
                bh[nt][0] = *(const uint32_t*)(p + A_WH);
                bh[nt][1] = *(const uint32_t*)(p + A_WH + 16);
                bl[nt][0] = *(const uint32_t*)(p + A_WL);
                bl[nt][1] = *(const uint32_t*)(p + A_WL + 16);
            }
#pragma unroll
            for (int mt = 0; mt < 2; mt++)
#pragma unroll
                for (int nt = 0; nt < 4; nt++) {
                    mma16816(d[mt][nt], ah[mt], bh[nt]);
                    mma16816(d[mt][nt], ah[mt], bl[nt]);
                    mma16816(d[mt][nt], al[mt], bh[nt]);
                }
        }
        __syncthreads();
    }

    // epilogue: d -> sL[t][k] (stride 65)
    float* sL = (float*)(sm + O_SL);
#pragma unroll
    for (int mt = 0; mt < 2; mt++)
#pragma unroll
        for (int nt = 0; nt < 4; nt++) {
            int r = wt + mt * 16 + (lane >> 2);
            int c = wk + nt * 8 + (lane & 3) * 2;
            sL[r * 65 + c]           = d[mt][nt][0];
            sL[r * 65 + c + 1]       = d[mt][nt][1];
            sL[(r + 8) * 65 + c]     = d[mt][nt][2];
            sL[(r + 8) * 65 + c + 1] = d[mt][nt][3];
        }
    __syncthreads();

    // softmax per t-row (threads 0..127), write to sT[k][t] (stride 132)
    float* sT = (float*)(sm + O_ST);
    if (tid < 128) {
        float a[64];
        const float* row = sL + tid * 65;
#pragma unroll
        for (int k = 0; k < 64; k++) a[k] = row[k] + sAux[k];
        float m = a[0];
#pragma unroll
        for (int k = 1; k < 64; k++) m = fmaxf(m, a[k]);
        float s = 0.f;
#pragma unroll
        for (int k = 0; k < 64; k++) { a[k] = __expf(a[k] - m); s += a[k]; }
        float inv = 1.f / s;
#pragma unroll
        for (int k = 0; k < 64; k++) sT[k * 132 + tid] = a[k] * inv;
    }
    __syncthreads();

    if (tid < KK) {
        float s = 0.f;
#pragma unroll 8
        for (int t = 0; t < 128; t++) s += sT[tid * 132 + t];
        g_asumP[(n * 8 + tile) * KK + tid] = s;
    }
    // convert + write a^T bf16 pairs [n][k][t]
#pragma unroll
    for (int it = 0; it < 4; it++) {
        int idx = tid + it * 256;
        int k = idx >> 4, seg = idx & 15, t = seg * 8;
        float4 v0 = *(float4*)&sT[k * 132 + t];
        float4 v1 = *(float4*)&sT[k * 132 + t + 4];
        __nv_bfloat162 h0, l0, h1, l1, h2, l2, h3, l3;
        split_pair(v0.x, v0.y, h0, l0);
        split_pair(v0.z, v0.w, h1, l1);
        split_pair(v1.x, v1.y, h2, l2);
        split_pair(v1.z, v1.w, h3, l3);
        size_t g = (size_t)(n * KK + k) * TT + t0 + t;
        *(uint4*)&g_aTh[g] = make_uint4(b2u(h0), b2u(h1), b2u(h2), b2u(h3));
        *(uint4*)&g_aTl[g] = make_uint4(b2u(l0), b2u(l1), b2u(l2), b2u(l3));
    }
}

// ---------------------------------------------------------------------------
// kB: vlad[64k x 128c] = sum_t a^T[k,t] x[t,c] (bf16 3-term split HMMA)
//     epilogue: - asum*cent, sq partials, store
// grid (4 c-tiles, 32 n), 256 threads (8 warps: 2 k-groups x 4 c-groups)
// ---------------------------------------------------------------------------
__global__ __launch_bounds__(256, 2) void kB(const float* __restrict__ x,
                                             const float* __restrict__ cent,
                                             float* __restrict__ out) {
    extern __shared__ __align__(16) char sm[];
    const int n = blockIdx.y, cb = blockIdx.x, c0 = cb * 128;
    const int tid = threadIdx.x, wid = tid >> 5, lane = tid & 31;
    const int wk = (wid & 1) * 32, wc = (wid >> 1) * 32;
    float* sAux = (float*)(sm + O_AUX);

    float d[2][4][4];
#pragma unroll
    for (int mt = 0; mt < 2; mt++)
#pragma unroll
        for (int nt = 0; nt < 4; nt++)
#pragma unroll
            for (int j = 0; j < 4; j++) d[mt][nt][j] = 0.f;

    const float* xn = x + (size_t)n * TT * CC + c0;
    const __nv_bfloat16* gah = g_aTh + (size_t)n * KK * TT;
    const __nv_bfloat16* gal = g_aTl + (size_t)n * KK * TT;

    for (int ch = 0; ch < 16; ch++) {
        // x chunk 64t x 128c -> transpose+split -> xT[c][t]
#pragma unroll
        for (int it = 0; it < 4; it++) {
            int idx = tid + it * 256;
            int c4 = idx & 31, tp = idx >> 5, t = tp * 2;
            const float* p = xn + (size_t)(ch * 64 + t) * CC + c4 * 4;
            float4 u = *(const float4*)p;
            float4 w = *(const float4*)(p + CC);
            float uf[4] = {u.x, u.y, u.z, u.w};
            float wf[4] = {w.x, w.y, w.z, w.w};
#pragma unroll
            for (int j = 0; j < 4; j++) {
                __nv_bfloat162 h, l;
                split_pair(uf[j], wf[j], h, l);     // (t, t+1) at row c
                uint32_t off = (uint32_t)((c4 * 4 + j) * STRB + t * 2);
                *(uint32_t*)(sm + B_XH + off) = b2u(h);
                *(uint32_t*)(sm + B_XL + off) = b2u(l);
            }
        }
        // a^T chunk 64k x 64t bf16 copy
#pragma unroll
        for (int it = 0; it < 2; it++) {
            int idx = tid + it * 256;
            int k = idx >> 3, seg = idx & 7;
            uint32_t off = (uint32_t)(k * STRB + seg * 16);
            *(uint4*)(sm + B_AH + off) = *(const uint4*)&gah[(size_t)k * TT + ch * 64 + seg * 8];
            *(uint4*)(sm + B_AL + off) = *(const uint4*)&gal[(size_t)k * TT + ch * 64 + seg * 8];
        }
        __syncthreads();

        const int ra = lane >> 2;
        const int tb2 = (lane & 3) * 2;
#pragma unroll
        for (int ks = 0; ks < 4; ks++) {
            int ts = ks * 16 + tb2;
            uint32_t ah[2][4], al[2][4];
#pragma unroll
            for (int mt = 0; mt < 2; mt++) {
                const char* p = sm + (wk + mt * 16 + ra) * STRB + ts * 2;
                ah[mt][0] = *(const uint32_t*)(p + B_AH);
                ah[mt][1] = *(const uint32_t*)(p + B_AH + 8 * STRB);
                ah[mt][2] = *(const uint32_t*)(p + B_AH + 16);
                ah[mt][3] = *(const uint32_t*)(p + B_AH + 8 * STRB + 16);
                al[mt][0] = *(const uint32_t*)(p + B_AL);
                al[mt][1] = *(const uint32_t*)(p + B_AL + 8 * STRB);
                al[mt][2] = *(const uint32_t*)(p + B_AL + 16);
                al[mt][3] = *(const uint32_t*)(p + B_AL + 8 * STRB + 16);
            }
            uint32_t bh[4][2], bl[4][2];
#pragma unroll
            for (int nt = 0; nt < 4; nt++) {
                const char* p = sm + (wc + nt * 8 + ra) * STRB + ts * 2;
                bh[nt][0] = *(const uint32_t*)(p + B_XH);
                bh[nt][1] = *(const uint32_t*)(p + B_XH + 16);
                bl[nt][0] = *(const uint32_t*)(p + B_XL);
                bl[nt][1] = *(const uint32_t*)(p + B_XL + 16);
            }
#pragma unroll
            for (int mt = 0; mt < 2; mt++)
#pragma unroll
                for (int nt = 0; nt < 4; nt++) {
                    mma16816(d[mt][nt], ah[mt], bh[nt]);
                    mma16816(d[mt][nt], ah[mt], bl[nt]);
                    mma16816(d[mt][nt], al[mt], bh[nt]);
                }
        }
        __syncthreads();
    }

    // epilogue: load cent tile + asum
    float* sC = (float*)(sm + O_SC);
    float* sO = (float*)(sm + O_SO);
    if (tid < KK) {
        float s = 0.f;
#pragma unroll
        for (int j = 0; j < 8; j++) s += g_asumP[(n * 8 + j) * KK + tid];
        sAux[tid] = s;
    }
#pragma unroll
    for (int it = 0; it < 8; it++) {
        int idx = tid + it * 256;
        int k = idx >> 5, c4 = idx & 31;
        *(float4*)&sC[k * 132 + c4 * 4] = *(const float4*)&cent[k * CC + c0 + c4 * 4];
    }
    __syncthreads();

    // v = d - asum[k]*cent[k][c] -> sO[k][c]
#pragma unroll
    for (int mt = 0; mt < 2; mt++)
#pragma unroll
        for (int nt = 0; nt < 4; nt++) {
            int k = wk + mt * 16 + (lane >> 2);
            int c = wc + nt * 8 + (lane & 3) * 2;
            float as0 = sAux[k], as1 = sAux[k + 8];
            sO[k * 132 + c]           = d[mt][nt][0] - as0 * sC[k * 132 + c];
            sO[k * 132 + c + 1]       = d[mt][nt][1] - as0 * sC[k * 132 + c + 1];
            sO[(k + 8) * 132 + c]     = d[mt][nt][2] - as1 * sC[(k + 8) * 132 + c];
            sO[(k + 8) * 132 + c + 1] = d[mt][nt][3] - as1 * sC[(k + 8) * 132 + c + 1];
        }
    __syncthreads();

    if (tid < KK) {
        float s = 0.f;
#pragma unroll 8
        for (int c = 0; c < 128; c++) { float v = sO[tid * 132 + c]; s = fmaf(v, v, s); }
        g_sqP[(n * 4 + cb) * KK + tid] = s;
    }
#pragma unroll
    for (int it = 0; it < 8; it++) {
        int idx = tid + it * 256;
        int k = idx >> 5, c4 = idx & 31;
        *(float4*)&out[(size_t)(n * KK + k) * CC + c0 + c4 * 4] = *(float4*)&sO[k * 132 + c4 * 4];
    }
}

// ---------------------------------------------------------------------------
// kN: intra + global L2 normalization in one RMW pass
// grid (32 n, 8 k-chunks), 256 threads
// ---------------------------------------------------------------------------
__global__ __launch_bounds__(256) void kN(float* __restrict__ out) {
    const int n = blockIdx.x, kc = blockIdx.y;
    const int tid = threadIdx.x;
    __shared__ float sInv[KK];
    __shared__ float sRed[2];
    __shared__ float sG;

    float contrib = 0.f;
    if (tid < KK) {
        float s = 0.f;
#pragma unroll
        for (int j = 0; j < 4; j++) s += g_sqP[(n * 4 + j) * KK + tid];
        float inv = 1.f / fmaxf(sqrtf(s), FEPS);
        sInv[tid] = inv;
        contrib = s * inv * inv;
#pragma unroll
        for (int o = 16; o > 0; o >>= 1) contrib += __shfl_xor_sync(0xffffffffu, contrib, o);
        if ((tid & 31) == 0) sRed[tid >> 5] = contrib;
    }
    __syncthreads();
    if (tid == 0) sG = 1.f / fmaxf(sqrtf(sRed[0] + sRed[1]), FEPS);
    __syncthreads();
    float g = sG;
#pragma unroll
    for (int it = 0; it < 4; it++) {
        int idx = tid + it * 256;
        int kl = idx >> 7, c4 = idx & 127;
        int k = kc * 8 + kl;
        float f = sInv[k] * g;
        float4* p = (float4*)&out[((size_t)n * KK + k) * CC + c4 * 4];
        float4 v = *p;
        v.x *= f; v.y *= f; v.z *= f; v.w *= f;
        *p = v;
    }
}

extern "C" void kernel_launch(void* const* d_in, const int* in_sizes, int n_in,
                              void* d_out, int out_size) {
    const float* x    = (const float*)d_in[0];  // [32,1024,512]
    const float* W    = (const float*)d_in[1];  // [64,512]
    const float* b    = (const float*)d_in[2];  // [64]
    const float* cent = (const float*)d_in[3];  // [64,512]
    float* out = (float*)d_out;

    cudaFuncSetAttribute(kA, cudaFuncAttributeMaxDynamicSharedMemorySize, SMEM_BYTES);
    cudaFuncSetAttribute(kB, cudaFuncAttributeMaxDynamicSharedMemorySize, SMEM_BYTES);

    kW<<<(KK * CC + 255) / 256, 256>>>(W);
    kA<<<dim3(8, NB), 256, SMEM_BYTES>>>(x, b);
    kB<<<dim3(4, NB), 256, SMEM_BYTES>>>(x, cent, out);
    kN<<<dim3(NB, 8), 256>>>(out);
}

// round 4
// speedup vs baseline: 2.2879x; 1.6191x over previous
#include <cuda_runtime.h>
#include <cuda_bf16.h>
#include <stdint.h>
#include <math.h>

#define NB 32
#define TT 1024
#define CC 512
#define KK 64
#define FEPS 1e-12f

#define STRB 144      // 64-col operand row stride bytes (36 words == 4 mod 32)
#define STRB2 272     // 128-col operand row stride bytes (68 words == 4 mod 32)

// kA smem (bytes)
#define A_XH 0                // 128 x 144 = 18432
#define A_XL 18432            // ends 36864
#define A_WH0 36864           // 64 x 144 = 9216
#define A_WL0 46080
#define A_WH1 55296
#define A_WL1 64512           // ends 73728
#define A_AUX 73728
#define SMEM_A 73984
// kA epilogue overlays (reuse operand region)
#define O_SL 0                // 128 x 65 f32 = 33280
#define O_ST 33280            // 64 x 132 f32 = 33792 (ends 67072)

// kB smem
#define B_XH 0                // 64 x 272 = 17408
#define B_XL 17408            // ends 34816
#define B_AH0 34816           // 64 x 144 = 9216
#define B_AL0 44032
#define B_AH1 53248
#define B_AL1 62464           // ends 71680
#define B_AUX 71680
#define SMEM_B 71936
#define O_SC 0                // 64 x 132 f32
#define O_SO 33792            // 64 x 132 f32 (ends 67584)

// ---- scratch ----
__device__ __align__(16) __nv_bfloat16 g_aTh[(size_t)NB * KK * TT];
__device__ __align__(16) __nv_bfloat16 g_aTl[(size_t)NB * KK * TT];
__device__ __align__(16) __nv_bfloat16 g_Wh[KK * CC];
__device__ __align__(16) __nv_bfloat16 g_Wl[KK * CC];
__device__ float g_asumP[NB * 8 * KK];
__device__ float g_sqP[NB * 4 * KK];

__device__ __forceinline__ uint32_t smem_u32(const void* p) {
    uint32_t a;
    asm("{ .reg .u64 t; cvta.to.shared.u64 t, %1; cvt.u32.u64 %0, t; }" : "=r"(a) : "l"(p));
    return a;
}
__device__ __forceinline__ uint32_t b2u(__nv_bfloat162 v) { return *reinterpret_cast<uint32_t*>(&v); }
__device__ __forceinline__ void split_pair(float f0, float f1, __nv_bfloat162& h, __nv_bfloat162& l) {
    h = __floats2bfloat162_rn(f0, f1);
    float2 hf = __bfloat1622float2(h);
    l = __floats2bfloat162_rn(f0 - hf.x, f1 - hf.y);
}
__device__ __forceinline__ void mma16816(float* d, const uint32_t* a, const uint32_t* b) {
    asm volatile("mma.sync.aligned.m16n8k16.row.col.f32.bf16.bf16.f32 "
                 "{%0,%1,%2,%3}, {%4,%5,%6,%7}, {%8,%9}, {%0,%1,%2,%3};"
                 : "+f"(d[0]), "+f"(d[1]), "+f"(d[2]), "+f"(d[3])
                 : "r"(a[0]), "r"(a[1]), "r"(a[2]), "r"(a[3]), "r"(b[0]), "r"(b[1]));
}
__device__ __forceinline__ void ldm4(uint32_t* r, uint32_t a) {
    asm volatile("ldmatrix.sync.aligned.m8n8.x4.shared.b16 {%0,%1,%2,%3}, [%4];"
                 : "=r"(r[0]), "=r"(r[1]), "=r"(r[2]), "=r"(r[3]) : "r"(a));
}
__device__ __forceinline__ void ldm4t(uint32_t* r, uint32_t a) {
    asm volatile("ldmatrix.sync.aligned.m8n8.x4.trans.shared.b16 {%0,%1,%2,%3}, [%4];"
                 : "=r"(r[0]), "=r"(r[1]), "=r"(r[2]), "=r"(r[3]) : "r"(a));
}
#define CPA16(dst, src) asm volatile("cp.async.ca.shared.global [%0], [%1], 16;" :: "r"(dst), "l"(src))
#define CPA_COMMIT() asm volatile("cp.async.commit_group;")
#define CPA_WAIT1() asm volatile("cp.async.wait_group 1;")
#define CPA_WAIT0() asm volatile("cp.async.wait_group 0;")

// ---------------------------------------------------------------------------
__global__ void kW(const float* __restrict__ W) {
    int i = blockIdx.x * 256 + threadIdx.x;
    if (i < KK * CC) {
        float v = W[i];
        __nv_bfloat16 h = __float2bfloat16(v);
        g_Wh[i] = h;
        g_Wl[i] = __float2bfloat16(v - __bfloat162float(h));
    }
}

// ---------------------------------------------------------------------------
// kA: logits[128t x 64k] = x @ W^T + bias, softmax -> a^T bf16 [n][k][t]
// grid (8, 32), 256 thr; pipelined: x via reg prefetch, W via cp.async 2-buf
// ---------------------------------------------------------------------------
__global__ __launch_bounds__(256, 2) void kA(const float* __restrict__ x,
                                             const float* __restrict__ b) {
    extern __shared__ __align__(16) char sm[];
    const int n = blockIdx.y, tile = blockIdx.x, t0 = tile * 128;
    const int tid = threadIdx.x, wid = tid >> 5, lane = tid & 31;
    const int wt = (wid & 3) * 32, wk = (wid >> 2) * 32;
    const uint32_t sbase = smem_u32(sm);
    float* sAux = (float*)(sm + A_AUX);
    if (tid < KK) sAux[tid] = b[tid];

    float d[2][4][4];
#pragma unroll
    for (int mt = 0; mt < 2; mt++)
#pragma unroll
        for (int nt = 0; nt < 4; nt++)
#pragma unroll
            for (int j = 0; j < 4; j++) d[mt][nt][j] = 0.f;

    const float* xn = x + ((size_t)n * TT + t0) * CC;
    const int xt = tid >> 4, xc4 = tid & 15;       // x load coords
    const int wk8 = tid >> 3, wseg = tid & 7;      // W copy coords

    // preload chunk 0
    float4 px[8];
#pragma unroll
    for (int it = 0; it < 8; it++)
        px[it] = *(const float4*)(xn + (size_t)(xt + it * 16) * CC + xc4 * 4);
    {
        uint32_t dh = sbase + A_WH0 + wk8 * STRB + wseg * 16;
#pragma unroll
        for (int q = 0; q < 2; q++) {
            int k = wk8 + q * 32;
            CPA16(dh + q * 32 * STRB, &g_Wh[k * CC + wseg * 8]);
            CPA16(dh + q * 32 * STRB + (A_WL0 - A_WH0), &g_Wl[k * CC + wseg * 8]);
        }
        CPA_COMMIT();
    }

#pragma unroll 1
    for (int ch = 0; ch < 8; ch++) {
        __syncthreads();
        // store x split -> smem [t][c]
#pragma unroll
        for (int it = 0; it < 8; it++) {
            __nv_bfloat162 h0, l0, h1, l1;
            split_pair(px[it].x, px[it].y, h0, l0);
            split_pair(px[it].z, px[it].w, h1, l1);
            uint32_t off = (uint32_t)((xt + it * 16) * STRB + xc4 * 8);
            *(uint2*)(sm + A_XH + off) = make_uint2(b2u(h0), b2u(h1));
            *(uint2*)(sm + A_XL + off) = make_uint2(b2u(l0), b2u(l1));
        }
        if (ch < 7) {
            // issue W(ch+1) + prefetch x(ch+1)
            uint32_t wb = ((ch + 1) & 1) ? A_WH1 : A_WH0;
            uint32_t dh = sbase + wb + wk8 * STRB + wseg * 16;
            int cn = (ch + 1) * 64;
#pragma unroll
            for (int q = 0; q < 2; q++) {
                int k = wk8 + q * 32;
                CPA16(dh + q * 32 * STRB, &g_Wh[k * CC + cn + wseg * 8]);
                CPA16(dh + q * 32 * STRB + 9216, &g_Wl[k * CC + cn + wseg * 8]);
            }
            CPA_COMMIT();
#pragma unroll
            for (int it = 0; it < 8; it++)
                px[it] = *(const float4*)(xn + (size_t)(xt + it * 16) * CC + cn + xc4 * 4);
            CPA_WAIT1();
        } else {
            CPA_WAIT0();
        }
        __syncthreads();

        const uint32_t wbase = sbase + ((ch & 1) ? A_WH1 : A_WH0);
#pragma unroll
        for (int ks = 0; ks < 4; ks++) {
            const int cs = ks * 16;
            uint32_t ah[2][4], al[2][4];
#pragma unroll
            for (int mt = 0; mt < 2; mt++) {
                uint32_t a = sbase + A_XH + (uint32_t)((wt + mt * 16 + (lane & 15)) * STRB
                              + (cs + ((lane >> 4) << 3)) * 2);
                ldm4(ah[mt], a);
                ldm4(al[mt], a + (A_XL - A_XH));
            }
            uint32_t bh[4][2], bl[4][2];
#pragma unroll
            for (int p = 0; p < 2; p++) {
                int g = lane >> 3;
                uint32_t a = wbase + (uint32_t)((wk + p * 16 + ((g >> 1) << 3) + (lane & 7)) * STRB
                              + (cs + ((g & 1) << 3)) * 2);
                uint32_t r[4];
                ldm4(r, a);
                bh[2 * p][0] = r[0]; bh[2 * p][1] = r[1];
                bh[2 * p + 1][0] = r[2]; bh[2 * p + 1][1] = r[3];
                ldm4(r, a + 9216);
                bl[2 * p][0] = r[0]; bl[2 * p][1] = r[1];
                bl[2 * p + 1][0] = r[2]; bl[2 * p + 1][1] = r[3];
            }
#pragma unroll
            for (int mt = 0; mt < 2; mt++)
#pragma unroll
                for (int nt = 0; nt < 4; nt++) {
                    mma16816(d[mt][nt], ah[mt], bh[nt]);
                    mma16816(d[mt][nt], ah[mt], bl[nt]);
                    mma16816(d[mt][nt], al[mt], bh[nt]);
                }
        }
    }
    __syncthreads();

    // epilogue: d -> sL[t][k]
    float* sL = (float*)(sm + O_SL);
#pragma unroll
    for (int mt = 0; mt < 2; mt++)
#pragma unroll
        for (int nt = 0; nt < 4; nt++) {
            int r = wt + mt * 16 + (lane >> 2);
            int c = wk + nt * 8 + (lane & 3) * 2;
            sL[r * 65 + c]           = d[mt][nt][0];
            sL[r * 65 + c + 1]       = d[mt][nt][1];
            sL[(r + 8) * 65 + c]     = d[mt][nt][2];
            sL[(r + 8) * 65 + c + 1] = d[mt][nt][3];
        }
    __syncthreads();

    float* sT = (float*)(sm + O_ST);
    if (tid < 128) {
        float a[64];
        const float* row = sL + tid * 65;
#pragma unroll
        for (int k = 0; k < 64; k++) a[k] = row[k] + sAux[k];
        float m = a[0];
#pragma unroll
        for (int k = 1; k < 64; k++) m = fmaxf(m, a[k]);
        float s = 0.f;
#pragma unroll
        for (int k = 0; k < 64; k++) { a[k] = __expf(a[k] - m); s += a[k]; }
        float inv = 1.f / s;
#pragma unroll
        for (int k = 0; k < 64; k++) sT[k * 132 + tid] = a[k] * inv;
    }
    __syncthreads();

    if (tid < KK) {
        float s = 0.f;
#pragma unroll 8
        for (int t = 0; t < 128; t++) s += sT[tid * 132 + t];
        g_asumP[(n * 8 + tile) * KK + tid] = s;
    }
#pragma unroll
    for (int it = 0; it < 4; it++) {
        int idx = tid + it * 256;
        int k = idx >> 4, seg = idx & 15, t = seg * 8;
        float4 v0 = *(float4*)&sT[k * 132 + t];
        float4 v1 = *(float4*)&sT[k * 132 + t + 4];
        __nv_bfloat162 h0, l0, h1, l1, h2, l2, h3, l3;
        split_pair(v0.x, v0.y, h0, l0);
        split_pair(v0.z, v0.w, h1, l1);
        split_pair(v1.x, v1.y, h2, l2);
        split_pair(v1.z, v1.w, h3, l3);
        size_t g = (size_t)(n * KK + k) * TT + t0 + t;
        *(uint4*)&g_aTh[g] = make_uint4(b2u(h0), b2u(h1), b2u(h2), b2u(h3));
        *(uint4*)&g_aTl[g] = make_uint4(b2u(l0), b2u(l1), b2u(l2), b2u(l3));
    }
}

// ---------------------------------------------------------------------------
// kB: vlad[64k x 128c] = sum_t aT[k][t] * x[t][c]; B frags via ldmatrix.trans
// grid (4, 32), 256 thr; x reg-prefetch, aT via cp.async 2-buf
// ---------------------------------------------------------------------------
__global__ __launch_bounds__(256, 2) void kB(const float* __restrict__ x,
                                             const float* __restrict__ cent,
                                             float* __restrict__ out) {
    extern __shared__ __align__(16) char sm[];
    const int n = blockIdx.y, cb = blockIdx.x, c0 = cb * 128;
    const int tid = threadIdx.x, wid = tid >> 5, lane = tid & 31;
    const int wk = (wid & 1) * 32, wc = (wid >> 1) * 32;
    const uint32_t sbase = smem_u32(sm);
    float* sAux = (float*)(sm + B_AUX);

    float d[2][4][4];
#pragma unroll
    for (int mt = 0; mt < 2; mt++)
#pragma unroll
        for (int nt = 0; nt < 4; nt++)
#pragma unroll
            for (int j = 0; j < 4; j++) d[mt][nt][j] = 0.f;

    const float* xn = x + (size_t)n * TT * CC + c0;
    const __nv_bfloat16* gah = g_aTh + (size_t)n * KK * TT;
    const __nv_bfloat16* gal = g_aTl + (size_t)n * KK * TT;
    const int xt = tid >> 5, xc4 = tid & 31;
    const int ak = tid >> 3, aseg = tid & 7;

    float4 px[8];
#pragma unroll
    for (int it = 0; it < 8; it++)
        px[it] = *(const float4*)(xn + (size_t)(xt + it * 8) * CC + xc4 * 4);
    {
        uint32_t dh = sbase + B_AH0 + ak * STRB + aseg * 16;
#pragma unroll
        for (int q = 0; q < 2; q++) {
            int k = ak + q * 32;
            CPA16(dh + q * 32 * STRB, &gah[(size_t)k * TT + aseg * 8]);
            CPA16(dh + q * 32 * STRB + 9216, &gal[(size_t)k * TT + aseg * 8]);
        }
        CPA_COMMIT();
    }

#pragma unroll 1
    for (int ch = 0; ch < 16; ch++) {
        __syncthreads();
#pragma unroll
        for (int it = 0; it < 8; it++) {
            __nv_bfloat162 h0, l0, h1, l1;
            split_pair(px[it].x, px[it].y, h0, l0);
            split_pair(px[it].z, px[it].w, h1, l1);
            uint32_t off = (uint32_t)((xt + it * 8) * STRB2 + xc4 * 8);
            *(uint2*)(sm + B_XH + off) = make_uint2(b2u(h0), b2u(h1));
            *(uint2*)(sm + B_XL + off) = make_uint2(b2u(l0), b2u(l1));
        }
        if (ch < 15) {
            uint32_t ab = ((ch + 1) & 1) ? B_AH1 : B_AH0;
            uint32_t dh = sbase + ab + ak * STRB + aseg * 16;
            int tn = (ch + 1) * 64;
#pragma unroll
            for (int q = 0; q < 2; q++) {
                int k = ak + q * 32;
                CPA16(dh + q * 32 * STRB, &gah[(size_t)k * TT + tn + aseg * 8]);
                CPA16(dh + q * 32 * STRB + 9216, &gal[(size_t)k * TT + tn + aseg * 8]);
            }
            CPA_COMMIT();
#pragma unroll
            for (int it = 0; it < 8; it++)
                px[it] = *(const float4*)(xn + (size_t)(tn + xt + it * 8) * CC + xc4 * 4);
            CPA_WAIT1();
        } else {
            CPA_WAIT0();
        }
        __syncthreads();

        const uint32_t abase = sbase + ((ch & 1) ? B_AH1 : B_AH0);
#pragma unroll
        for (int ks = 0; ks < 4; ks++) {
            const int ts = ks * 16;
            uint32_t ah[2][4], al[2][4];
#pragma unroll
            for (int mt = 0; mt < 2; mt++) {
                uint32_t a = abase + (uint32_t)((wk + mt * 16 + (lane & 15)) * STRB
                              + (ts + ((lane >> 4) << 3)) * 2);
                ldm4(ah[mt], a);
                ldm4(al[mt], a + 9216);
            }
            uint32_t bh[4][2], bl[4][2];
#pragma unroll
            for (int p = 0; p < 2; p++) {
                int g = lane >> 3;
                uint32_t a = sbase + B_XH + (uint32_t)((ts + ((g & 1) << 3) + (lane & 7)) * STRB2
                              + (wc + p * 16 + ((g >> 1) << 3)) * 2);
                uint32_t r[4];
                ldm4t(r, a);
                bh[2 * p][0] = r[0]; bh[2 * p][1] = r[1];
                bh[2 * p + 1][0] = r[2]; bh[2 * p + 1][1] = r[3];
                ldm4t(r, a + (B_XL - B_XH));
                bl[2 * p][0] = r[0]; bl[2 * p][1] = r[1];
                bl[2 * p + 1][0] = r[2]; bl[2 * p + 1][1] = r[3];
            }
#pragma unroll
            for (int mt = 0; mt < 2; mt++)
#pragma unroll
                for (int nt = 0; nt < 4; nt++) {
                    mma16816(d[mt][nt], ah[mt], bh[nt]);
                    mma16816(d[mt][nt], ah[mt], bl[nt]);
                    mma16816(d[mt][nt], al[mt], bh[nt]);
                }
        }
    }
    __syncthreads();

    // epilogue
    float* sC = (float*)(sm + O_SC);
    float* sO = (float*)(sm + O_SO);
    if (tid < KK) {
        float s = 0.f;
#pragma unroll
        for (int j = 0; j < 8; j++) s += g_asumP[(n * 8 + j) * KK + tid];
        sAux[tid] = s;
    }
#pragma unroll
    for (int it = 0; it < 8; it++) {
        int idx = tid + it * 256;
        int k = idx >> 5, c4 = idx & 31;
        *(float4*)&sC[k * 132 + c4 * 4] = *(const float4*)&cent[k * CC + c0 + c4 * 4];
    }
    __syncthreads();

#pragma unroll
    for (int mt = 0; mt < 2; mt++)
#pragma unroll
        for (int nt = 0; nt < 4; nt++) {
            int k = wk + mt * 16 + (lane >> 2);
            int c = wc + nt * 8 + (lane & 3) * 2;
            float as0 = sAux[k], as1 = sAux[k + 8];
            sO[k * 132 + c]           = d[mt][nt][0] - as0 * sC[k * 132 + c];
            sO[k * 132 + c + 1]       = d[mt][nt][1] - as0 * sC[k * 132 + c + 1];
            sO[(k + 8) * 132 + c]     = d[mt][nt][2] - as1 * sC[(k + 8) * 132 + c];
            sO[(k + 8) * 132 + c + 1] = d[mt][nt][3] - as1 * sC[(k + 8) * 132 + c + 1];
        }
    __syncthreads();

    if (tid < KK) {
        float s = 0.f;
#pragma unroll 8
        for (int c = 0; c < 128; c++) { float v = sO[tid * 132 + c]; s = fmaf(v, v, s); }
        g_sqP[(n * 4 + cb) * KK + tid] = s;
    }
#pragma unroll
    for (int it = 0; it < 8; it++) {
        int idx = tid + it * 256;
        int k = idx >> 5, c4 = idx & 31;
        *(float4*)&out[(size_t)(n * KK + k) * CC + c0 + c4 * 4] = *(float4*)&sO[k * 132 + c4 * 4];
    }
}

// ---------------------------------------------------------------------------
__global__ __launch_bounds__(256) void kN(float* __restrict__ out) {
    const int n = blockIdx.x, kc = blockIdx.y;
    const int tid = threadIdx.x;
    __shared__ float sInv[KK];
    __shared__ float sRed[2];
    __shared__ float sG;

    float contrib = 0.f;
    if (tid < KK) {
        float s = 0.f;
#pragma unroll
        for (int j = 0; j < 4; j++) s += g_sqP[(n * 4 + j) * KK + tid];
        float inv = 1.f / fmaxf(sqrtf(s), FEPS);
        sInv[tid] = inv;
        contrib = s * inv * inv;
#pragma unroll
        for (int o = 16; o > 0; o >>= 1) contrib += __shfl_xor_sync(0xffffffffu, contrib, o);
        if ((tid & 31) == 0) sRed[tid >> 5] = contrib;
    }
    __syncthreads();
    if (tid == 0) sG = 1.f / fmaxf(sqrtf(sRed[0] + sRed[1]), FEPS);
    __syncthreads();
    float g = sG;
#pragma unroll
    for (int it = 0; it < 4; it++) {
        int idx = tid + it * 256;
        int kl = idx >> 7, c4 = idx & 127;
        int k = kc * 8 + kl;
        float f = sInv[k] * g;
        float4* p = (float4*)&out[((size_t)n * KK + k) * CC + c4 * 4];
        float4 v = *p;
        v.x *= f; v.y *= f; v.z *= f; v.w *= f;
        *p = v;
    }
}

extern "C" void kernel_launch(void* const* d_in, const int* in_sizes, int n_in,
                              void* d_out, int out_size) {
    const float* x    = (const float*)d_in[0];
    const float* W    = (const float*)d_in[1];
    const float* b    = (const float*)d_in[2];
    const float* cent = (const float*)d_in[3];
    float* out = (float*)d_out;

    cudaFuncSetAttribute(kA, cudaFuncAttributeMaxDynamicSharedMemorySize, SMEM_A);
    cudaFuncSetAttribute(kB, cudaFuncAttributeMaxDynamicSharedMemorySize, SMEM_B);

    kW<<<(KK * CC + 255) / 256, 256>>>(W);
    kA<<<dim3(8, NB), 256, SMEM_A>>>(x, b);
    kB<<<dim3(4, NB), 256, SMEM_B>>>(x, cent, out);
    kN<<<dim3(NB, 8), 256>>>(out);
}